// round 16
// baseline (speedup 1.0000x reference)
#include <cuda_runtime.h>
#include <cuda_fp16.h>
#include <cstdint>
#include <cstddef>

#define INNER 31999
#define VOCAB 32000
#define DEPTH 18
#define NROWS 64          // B*T
#define KDIM  512
#define MT    128         // nodes per block tile
#define KC    64          // K elems per chunk
#define NCHUNK (KDIM / KC)       // 8
// smem layout (224KB, occ 1):
//   [0]       B fp16 resident, full K:   64 rows * 1024B = 64KB
//   [65536]   A32 ring: 4 stages * 32KB (128 rows * 256B fp32)
//   [196608]  A16 double buffer: 2 * 16KB (128 rows * 128B fp16)
#define B_OFF   0
#define A32_OFF 65536
#define A32_ST  32768
#define A16_OFF 196608
#define A16_ST  16384
#define SMEM_TOTAL 229376

// Log-prob table: [2*node + side][row], fp16. side 0 = log sigma, side 1 = log(1-sigma).
__device__ __half g_L[(size_t)2 * VOCAB * NROWS];

// ---------------- helpers ----------------
__device__ __forceinline__ uint32_t smem_u32(const void* p) {
    return (uint32_t)__cvta_generic_to_shared(p);
}
__device__ __forceinline__ void cp_async16z(uint32_t dst, const void* src, int srcBytes) {
    asm volatile("cp.async.cg.shared.global [%0], [%1], 16, %2;"
                 :: "r"(dst), "l"(src), "r"(srcBytes));
}
__device__ __forceinline__ void cp_commit() { asm volatile("cp.async.commit_group;"); }
template<int N> __device__ __forceinline__ void cp_wait() { asm volatile("cp.async.wait_group %0;" :: "n"(N)); }

__device__ __forceinline__ void ldsm4(uint32_t& r0, uint32_t& r1, uint32_t& r2, uint32_t& r3,
                                      uint32_t addr) {
    asm volatile("ldmatrix.sync.aligned.m8n8.x4.shared.b16 {%0,%1,%2,%3}, [%4];"
                 : "=r"(r0), "=r"(r1), "=r"(r2), "=r"(r3) : "r"(addr));
}
__device__ __forceinline__ void mma_f16(float* c, const uint32_t* a, const uint32_t* b) {
    asm volatile(
        "mma.sync.aligned.m16n8k16.row.col.f32.f16.f16.f32 "
        "{%0,%1,%2,%3}, {%4,%5,%6,%7}, {%8,%9}, {%0,%1,%2,%3};"
        : "+f"(c[0]), "+f"(c[1]), "+f"(c[2]), "+f"(c[3])
        : "r"(a[0]), "r"(a[1]), "r"(a[2]), "r"(a[3]), "r"(b[0]), "r"(b[1]));
}
__device__ __forceinline__ void sts64(uint32_t off, __half2 p0, __half2 p1) {
    asm volatile("st.shared.v2.b32 [%0], {%1, %2};"
                 :: "r"(off), "r"(*(uint32_t*)&p0), "r"(*(uint32_t*)&p1));
}

// ---------------------------------------------------------------------------
// Kernel 1: C[128 nodes, 64 rows] per block = W_tile @ att^T, fp16 m16n8k16.
// DEEP PIPELINE: W streams fp32 via cp.async.cg into a 4-stage 32KB ring
// (fire-and-forget, ~96KB in flight); fp32->fp16 cvt is smem->smem into a
// 16KB double buffer, overlapping compute. B (att) fp16-resident full-K.
// 256 thr, 8 warps (4M x 2N), warp tile 32M x 32N, occ 1 (224KB smem).
// ---------------------------------------------------------------------------
__global__ __launch_bounds__(256, 1) void hs_gemm_kernel(
    const float* __restrict__ att, const float* __restrict__ W)
{
    extern __shared__ char smem[];
    const uint32_t sb    = smem_u32(smem);
    const uint32_t sbA32 = sb + A32_OFF;
    const uint32_t sbA16 = sb + A16_OFF;

    const int tid   = threadIdx.x;
    const int lane  = tid & 31;
    const int warp  = tid >> 5;
    const int wm    = warp & 3;        // warp M index (rows wm*32..+31)
    const int wn    = warp >> 2;       // warp N index (cols wn*32..+31)
    const int nbase = blockIdx.x * MT;
    const int gid   = lane >> 2;
    const int tig   = lane & 3;

    // -------- B prologue: att [64x512] fp32 -> fp16 smem, swizzled (as r15) ----
#pragma unroll
    for (int i = 0; i < 32; i++) {
        int u = tid + i * 256;
        int row = u >> 7, f4 = u & 127;
        float4 v = __ldcg(reinterpret_cast<const float4*>(att + (size_t)row * KDIM + f4 * 4));
        uint32_t unit = (uint32_t)((f4 >> 1) ^ (row & 7));
        uint32_t off  = sb + (uint32_t)(row * 1024) + unit * 16 + (uint32_t)(f4 & 1) * 8;
        sts64(off, __floats2half2_rn(v.x, v.y), __floats2half2_rn(v.z, v.w));
    }

    // -------- A32 stage loader: chunk t -> ring slot t&3 (raw fp32, no regs) ----
    auto ldA32 = [&](int t) {
        const uint32_t base = sbA32 + (uint32_t)(t & 3) * A32_ST;
#pragma unroll
        for (int i = 0; i < 8; i++) {            // 128 rows x 16 float4 = 2048
            int u = tid + i * 256;
            int row = u >> 4, j = u & 15;
            int  wr = nbase + row;
            bool v  = (wr < INNER);
            cp_async16z(base + (uint32_t)(row * 256 + j * 16),
                        W + (size_t)(v ? wr : 0) * KDIM + t * KC + j * 4, v ? 16 : 0);
        }
        cp_commit();
    };

    // -------- cvt: A32 slot (t&3) -> A16 buffer (t&1), swizzled fp16 ----------
    auto cvtA = [&](int t) {
        const char* src = smem + A32_OFF + (size_t)(t & 3) * A32_ST;
        const uint32_t dst = sbA16 + (uint32_t)(t & 1) * A16_ST;
#pragma unroll
        for (int i = 0; i < 8; i++) {
            int u = tid + i * 256;
            int row = u >> 4, j = u & 15;
            float4 v = *reinterpret_cast<const float4*>(src + row * 256 + j * 16);
            uint32_t unit = (uint32_t)((j >> 1) ^ (row & 7));
            uint32_t off  = dst + (uint32_t)(row * 128) + unit * 16 + (uint32_t)(j & 1) * 8;
            sts64(off, __floats2half2_rn(v.x, v.y), __floats2half2_rn(v.z, v.w));
        }
    };

    // -------- ldmatrix per-lane address precompute (r15 mapping) --------
    const int li = lane >> 3;
    const int lr = lane & 7;
    const uint32_t kh = (uint32_t)(li >> 1);     // k 16B-half select
    uint32_t aBase[2], aX[2];
#pragma unroll
    for (int mt = 0; mt < 2; mt++) {
        int row = wm * 32 + mt * 16 + lr + ((li & 1) << 3);
        aBase[mt] = sbA16 + (uint32_t)(row * 128);
        aX[mt]    = (uint32_t)(row & 7);
    }
    uint32_t bBase[2], bX[2];
#pragma unroll
    for (int q = 0; q < 2; q++) {
        int row = wn * 32 + q * 16 + lr + ((li & 1) << 3);
        bBase[q] = sb + (uint32_t)(row * 1024);
        bX[q]    = (uint32_t)(row & 7);
    }

    float acc[2][4][4];
#pragma unroll
    for (int mt = 0; mt < 2; mt++)
#pragma unroll
        for (int f = 0; f < 4; f++)
#pragma unroll
            for (int c = 0; c < 4; c++) acc[mt][f][c] = 0.0f;

    // -------- prologue: 3 A32 stages in flight, cvt chunk 0 --------
    ldA32(0); ldA32(1); ldA32(2);
    cp_wait<2>();                                // A32(0) landed (own copies)
    __syncthreads();                             // visibility: B + A32(0)
    cvtA(0);                                     // fill A16 buf 0
    // NOTE: loop-top sync provides visibility of cvtA(0) before compute(0)

    for (int t = 0; t < NCHUNK; t++) {
        if (t + 3 < NCHUNK) ldA32(t + 3);        // slot (t-1)&3: consumed 2 syncs ago
        // guarantee A32(t+1) complete before cvt(t+1)
        if      (t <= NCHUNK - 4) cp_wait<2>();
        else if (t == NCHUNK - 3) cp_wait<1>();
        else                      cp_wait<0>();
        __syncthreads();                         // A32(t+1) + cvtA(t) visible to all

        if (t + 1 < NCHUNK) cvtA(t + 1);         // overlaps compute below

        const uint32_t Ab = (uint32_t)(t & 1) * A16_ST;
#pragma unroll
        for (int ks = 0; ks < 4; ks++) {         // 4 x k16 per chunk
            uint32_t a[2][4];
#pragma unroll
            for (int mt = 0; mt < 2; mt++)
                ldsm4(a[mt][0], a[mt][1], a[mt][2], a[mt][3],
                      aBase[mt] + Ab + ((((uint32_t)(ks * 2) + kh) ^ aX[mt]) << 4));
            uint32_t b[4][2];
            const uint32_t ksg2 = (uint32_t)(t * 8 + ks * 2);
#pragma unroll
            for (int q = 0; q < 2; q++) {
                uint32_t r0, r1, r2, r3;
                ldsm4(r0, r1, r2, r3, bBase[q] + (((ksg2 + kh) ^ bX[q]) << 4));
                b[q * 2][0] = r0;     b[q * 2][1] = r2;
                b[q * 2 + 1][0] = r1; b[q * 2 + 1][1] = r3;
            }
#pragma unroll
            for (int mt = 0; mt < 2; mt++)
#pragma unroll
                for (int f = 0; f < 4; f++)
                    mma_f16(acc[mt][f], a[mt], b[f]);
        }
        __syncthreads();                         // cvtA(t+1) done before next compute
    }

    // -------- epilogue: softplus -> fp16, smem transpose (swizzled), flat copy ----
#pragma unroll
    for (int mt = 0; mt < 2; mt++) {
#pragma unroll
        for (int m8 = 0; m8 < 2; m8++) {
            const int nl = wm * 32 + mt * 16 + m8 * 8 + gid;     // local node 0..127
            const uint32_t swz = (uint32_t)((nl & 7) << 4);
#pragma unroll
            for (int f = 0; f < 4; f++) {
                float lp[2], ln[2];
#pragma unroll
                for (int u = 0; u < 2; u++) {
                    float h = acc[mt][f][m8 * 2 + u];
                    float l = __logf(1.0f + __expf(-fabsf(h)));
                    lp[u] = fmaxf(fminf(h, 0.0f) - l, -20.7232658f);   // log sigma
                    ln[u] = fmaxf(-fmaxf(h, 0.0f) - l, -20.7232658f);  // log(1-sigma)
                }
                const uint32_t col = (uint32_t)(wn * 64 + f * 16 + tig * 4) ^ swz;
                *reinterpret_cast<__half2*>(smem + (2 * nl)     * 128 + col) = __floats2half2_rn(lp[0], lp[1]);
                *reinterpret_cast<__half2*>(smem + (2 * nl + 1) * 128 + col) = __floats2half2_rn(ln[0], ln[1]);
            }
        }
    }
    __syncthreads();

    char* gdst = reinterpret_cast<char*>(&g_L[(size_t)(2 * nbase) * NROWS]);
#pragma unroll
    for (int i = 0; i < 8; i++) {
        int u = tid + i * 256;               // 16B unit, 0..2047
        int s = u >> 3, j = u & 7;
        uint32_t soff = (uint32_t)(s * 128 + ((j ^ ((s >> 1) & 7)) << 4));
        uint4 v = *reinterpret_cast<const uint4*>(smem + soff);
        __stcg(reinterpret_cast<uint4*>(gdst + (size_t)u * 16), v);
    }
}

// ---------------------------------------------------------------------------
// Kernel 2 (r10 best shape + L1 bypass): 32 words per block (8 warps x 4),
// 256 threads, grid 1000. 18 batched LDG.128 via __ldcg (L2-only),
// pairwise HADD2 + fp32 flush. smem transpose for coalesced float4 output.
// ---------------------------------------------------------------------------
#define GWPB 32
__global__ __launch_bounds__(256) void hs_gather_kernel(
    const int* __restrict__ pidx, const float* __restrict__ psign,
    float* __restrict__ out)
{
    __shared__ uint16_t sci[GWPB * DEPTH];      // 576 packed child indices
    __shared__ float tr[NROWS * (GWPB + 1)];    // [row][word], pad 33

    const int tid   = threadIdx.x;
    const int lane  = tid & 31;
    const int warp  = tid >> 5;
    const int g     = lane >> 3;                 // word-in-warp 0..3
    const int sub   = lane & 7;                  // 16B sub-chunk -> rows 8*sub..+7
    const int wbase = blockIdx.x * GWPB;

    for (int j = tid; j < GWPB * DEPTH; j += 256) {
        int gj = wbase * DEPTH + j;
        sci[j] = (uint16_t)(2 * pidx[gj] + (psign[gj] < 0.0f ? 1 : 0));
    }
    __syncthreads();

    const int wloc = warp * 4 + g;               // word within block 0..31

    // Batch all 18 row-chunk loads (independent -> deep MLP), L2-only
    uint4 v[DEPTH];
#pragma unroll
    for (int d = 0; d < DEPTH; d++) {
        int ci = sci[wloc * DEPTH + d];
        v[d] = __ldcg(reinterpret_cast<const uint4*>(&g_L[(size_t)ci * NROWS]) + sub);
    }

    // Reduce: pairwise fp16 add, then fp32 accumulate (9 flushes)
    float acc[8] = {0.f, 0.f, 0.f, 0.f, 0.f, 0.f, 0.f, 0.f};
#pragma unroll
    for (int p = 0; p < DEPTH / 2; p++) {
        const uint4 a = v[2 * p], b = v[2 * p + 1];
        __half2 s0 = __hadd2(*(const __half2*)&a.x, *(const __half2*)&b.x);
        __half2 s1 = __hadd2(*(const __half2*)&a.y, *(const __half2*)&b.y);
        __half2 s2 = __hadd2(*(const __half2*)&a.z, *(const __half2*)&b.z);
        __half2 s3 = __hadd2(*(const __half2*)&a.w, *(const __half2*)&b.w);
        float2 f0 = __half22float2(s0); acc[0] += f0.x; acc[1] += f0.y;
        float2 f1 = __half22float2(s1); acc[2] += f1.x; acc[3] += f1.y;
        float2 f2 = __half22float2(s2); acc[4] += f2.x; acc[5] += f2.y;
        float2 f3 = __half22float2(s3); acc[6] += f3.x; acc[7] += f3.y;
    }

    // rows 8*sub + r, word wloc
#pragma unroll
    for (int r = 0; r < 8; r++)
        tr[(8 * sub + r) * (GWPB + 1) + wloc] = acc[r];
    __syncthreads();

    // 64 rows x 32 words = 2048 floats = 512 float4; 2 per thread
#pragma unroll
    for (int i = 0; i < 2; i++) {
        int u   = tid + i * 256;
        int row = u >> 3;
        int q   = (u & 7) * 4;
        float4 o = make_float4(tr[row * (GWPB + 1) + q],     tr[row * (GWPB + 1) + q + 1],
                               tr[row * (GWPB + 1) + q + 2], tr[row * (GWPB + 1) + q + 3]);
        *reinterpret_cast<float4*>(out + (size_t)row * VOCAB + wbase + q) = o;
    }
}

extern "C" void kernel_launch(void* const* d_in, const int* in_sizes, int n_in,
                              void* d_out, int out_size)
{
    (void)in_sizes; (void)n_in; (void)out_size;
    const float* att   = (const float*)d_in[0];
    const float* W     = (const float*)d_in[1];
    const int*   pidx  = (const int*)d_in[2];
    const float* psign = (const float*)d_in[3];
    float* out = (float*)d_out;

    cudaFuncSetAttribute(hs_gemm_kernel, cudaFuncAttributeMaxDynamicSharedMemorySize, SMEM_TOTAL);
    hs_gemm_kernel<<<(INNER + MT - 1) / MT, 256, SMEM_TOTAL>>>(att, W);
    hs_gather_kernel<<<VOCAB / GWPB, 256>>>(pidx, psign, out);
}